// round 7
// baseline (speedup 1.0000x reference)
#include <cuda_runtime.h>
#include <cstdint>

// QuantLinear 4-bit matvec, GB300 (sm_103a) — R5 (R4 resubmit, infra failed)
//   y[o] = bias[o] + scales[o] * sum_k x[k]*w[k,o] - zeros[o] * sum_k x[k]
//   w[r*8+j, o] = (qweight[r,o] >> 4j) & 0xF
//
// R1-R3 pinned at ~2.4TB/s regardless of occupancy -> per-warp MLP bound
// (loop-carried load). R5: explicit 4-deep register prefetch (loads
// independent of the dp2a chain), 512 CTAs via in-kernel split-K (grid
// 128x4), integer partials + self-resetting atomic ticket so the last CTA
// per output group applies the fused epilogue (no second launch; R2 showed
// a second launch costs ~5us). Streaming loads via __ldcs. dp2a scheme
// integer-exact and deterministic (rel_err ~9.5e-5 every round).

#define K_IN    8192
#define N_OUT   8192
#define NW4     (N_OUT / 4)     // uint4 per qweight row = 2048
#define RW      1024            // qweight rows
#define KSPLIT  4
#define RW_BLK  (RW / KSPLIT)   // 256 rows per k-block
#define XSF     6553.0f

__device__ int      g_part[KSPLIT][N_OUT];  // int partials (every slot written each launch)
__device__ int      g_xsum[KSPLIT];         // int x-chunk sums (idempotent dup writes)
__device__ unsigned g_tick[N_OUT / 64];     // arrival tickets; reset to 0 by last CTA

__device__ __forceinline__ int dp2a_lo(int a, unsigned b, int c) {
    int d;
    asm("dp2a.lo.s32.u32 %0, %1, %2, %3;" : "=r"(d) : "r"(a), "r"(b), "r"(c));
    return d;
}
__device__ __forceinline__ int dp2a_hi(int a, unsigned b, int c) {
    int d;
    asm("dp2a.hi.s32.u32 %0, %1, %2, %3;" : "=r"(d) : "r"(a), "r"(b), "r"(c));
    return d;
}

__global__ __launch_bounds__(256, 4)
void qlin4_kernel(const float* __restrict__ x,
                  const uint4* __restrict__ qw,     // [RW, NW4]
                  const float* __restrict__ scales,
                  const float* __restrict__ zeros,
                  const float* __restrict__ bias,
                  float* __restrict__ out)
{
    // Packed int16 x chunk (256 local rows), dp2a byte-lane order per group:
    // { (x0|x2), (x4|x6), (x1|x3), (x5|x7) }
    __shared__ int4 sxp[RW_BLK];      // 4 KB
    __shared__ int4 sred4[16 * 16];   // 4 KB: [kslice][oq] int partials
    __shared__ int  sr32[8];
    __shared__ unsigned s_old;

    const int tid = threadIdx.x;
    const int bx  = blockIdx.x;       // output group (64 outputs)
    const int kb  = blockIdx.y;       // k-block (256 qweight rows)

    // ---- Phase 1: quantize + pack this k-block's 2048 x values ----
    {
        const int g = tid;            // local row (8 x values)
        const float4* xp4 = (const float4*)x + (kb * RW_BLK + g) * 2;
        float4 a = __ldg(xp4);
        float4 b = __ldg(xp4 + 1);
        int q0 = __float2int_rn(a.x * XSF);
        int q1 = __float2int_rn(a.y * XSF);
        int q2 = __float2int_rn(a.z * XSF);
        int q3 = __float2int_rn(a.w * XSF);
        int q4 = __float2int_rn(b.x * XSF);
        int q5 = __float2int_rn(b.y * XSF);
        int q6 = __float2int_rn(b.z * XSF);
        int q7 = __float2int_rn(b.w * XSF);
        int4 p;
        p.x = (q0 & 0xFFFF) | (q2 << 16);
        p.y = (q4 & 0xFFFF) | (q6 << 16);
        p.z = (q1 & 0xFFFF) | (q3 << 16);
        p.w = (q5 & 0xFFFF) | (q7 << 16);
        sxp[g] = p;

        int s16 = q0 + q1 + q2 + q3 + q4 + q5 + q6 + q7;
#pragma unroll
        for (int off = 16; off > 0; off >>= 1)
            s16 += __shfl_xor_sync(0xFFFFFFFFu, s16, off);
        if ((tid & 31) == 0) sr32[tid >> 5] = s16;
    }
    __syncthreads();
    if (tid == 0) {
        int t = 0;
#pragma unroll
        for (int w = 0; w < 8; w++) t += sr32[w];
        g_xsum[kb] = t;   // duplicate identical writes across bx: benign
    }

    // ---- Phase 2: stream 256 qweight rows, 4-deep register prefetch ----
    // oq in [0,16): uint4 column (half-warp = 256B contiguous, 2 full lines);
    // ks in [0,16): 16-row K slice.
    const int oq = tid & 15;
    const int ks = tid >> 4;
    const uint4* base = qw + (size_t)(kb * RW_BLK + ks * 16) * NW4
                           + (bx * 16 + oq);

    uint4 f0 = __ldcs(base + 0 * NW4);
    uint4 f1 = __ldcs(base + 1 * NW4);
    uint4 f2 = __ldcs(base + 2 * NW4);
    uint4 f3 = __ldcs(base + 3 * NW4);

    int a0 = 0, a1 = 0, a2 = 0, a3 = 0;
#pragma unroll
    for (int rr = 0; rr < 16; rr++) {
        uint4 q = f0;                       // consume oldest
        f0 = f1; f1 = f2; f2 = f3;          // rotate (register-renamed, free)
        // branch-free prefetch: clamp to last row (redundant L1-hit loads for
        // the final 4 iterations instead of a predicated branch in the loop)
        const int pre = (rr + 4 < 16) ? (rr + 4) : 15;
        f3 = __ldcs(base + pre * NW4);

        int4 xp = sxp[ks * 16 + rr];        // broadcast LDS.128, conflict-free

        unsigned lo, hi;
        lo = q.x & 0x0F0F0F0Fu; hi = (q.x >> 4) & 0x0F0F0F0Fu;
        a0 = dp2a_lo(xp.x, lo, a0); a0 = dp2a_hi(xp.y, lo, a0);
        a0 = dp2a_lo(xp.z, hi, a0); a0 = dp2a_hi(xp.w, hi, a0);

        lo = q.y & 0x0F0F0F0Fu; hi = (q.y >> 4) & 0x0F0F0F0Fu;
        a1 = dp2a_lo(xp.x, lo, a1); a1 = dp2a_hi(xp.y, lo, a1);
        a1 = dp2a_lo(xp.z, hi, a1); a1 = dp2a_hi(xp.w, hi, a1);

        lo = q.z & 0x0F0F0F0Fu; hi = (q.z >> 4) & 0x0F0F0F0Fu;
        a2 = dp2a_lo(xp.x, lo, a2); a2 = dp2a_hi(xp.y, lo, a2);
        a2 = dp2a_lo(xp.z, hi, a2); a2 = dp2a_hi(xp.w, hi, a2);

        lo = q.w & 0x0F0F0F0Fu; hi = (q.w >> 4) & 0x0F0F0F0Fu;
        a3 = dp2a_lo(xp.x, lo, a3); a3 = dp2a_hi(xp.y, lo, a3);
        a3 = dp2a_lo(xp.z, hi, a3); a3 = dp2a_hi(xp.w, hi, a3);
    }
    sred4[ks * 16 + oq] = make_int4(a0, a1, a2, a3);
    __syncthreads();

    // ---- Phase 3: intra-CTA reduce over 16 k-slices, publish partial ----
    if (tid < 64) {
        const int* sr = (const int*)sred4;   // [16][64]
        int s = 0;
#pragma unroll
        for (int k2 = 0; k2 < 16; k2++) s += sr[k2 * 64 + tid];
        g_part[kb][bx * 64 + tid] = s;
        __threadfence();                      // release: partial + g_xsum visible
    }
    __syncthreads();

    // ---- Phase 4: ticket; last-arriving CTA of this bx does the epilogue ----
    if (tid == 0) s_old = atomicAdd(&g_tick[bx], 1u);
    __syncthreads();
    if (s_old == KSPLIT - 1) {
        __threadfence();                      // acquire
        if (tid == 0) g_tick[bx] = 0;         // self-reset for next launch
        if (tid < 64) {
            const int o = bx * 64 + tid;
            int s  = g_part[0][o] + g_part[1][o] + g_part[2][o] + g_part[3][o];
            int xs = g_xsum[0] + g_xsum[1] + g_xsum[2] + g_xsum[3];
            const float inv = 1.0f / XSF;
            float xw   = (float)s  * inv;
            float xsum = (float)xs * inv;
            out[o] = __ldg(bias + o) + __ldg(scales + o) * xw
                                     - __ldg(zeros  + o) * xsum;
        }
    }
}

extern "C" void kernel_launch(void* const* d_in, const int* in_sizes, int n_in,
                              void* d_out, int out_size)
{
    // metadata order: x, qweight, scales, zeros, bias
    const float* x      = (const float*)d_in[0];
    const uint4* qw     = (const uint4*)d_in[1];
    const float* scales = (const float*)d_in[2];
    const float* zeros  = (const float*)d_in[3];
    const float* bias   = (const float*)d_in[4];
    float* out          = (float*)d_out;

    qlin4_kernel<<<dim3(N_OUT / 64, KSPLIT), 256>>>(x, qw, scales, zeros, bias, out);
}

// round 8
// speedup vs baseline: 1.0310x; 1.0310x over previous
#include <cuda_runtime.h>
#include <cstdint>

// QuantLinear 4-bit matvec, GB300 (sm_103a) — R8: row-contiguous streaming
//   y[o] = bias[o] + scales[o] * sum_k x[k]*w[k,o] - zeros[o] * sum_k x[k]
//   w[r*8+j, o] = (qweight[r,o] >> 4j) & 0xF
//
// R1-R7: HBM pinned at ~2.3-2.5 TB/s across occ 12%->37% and explicit 4-deep
// prefetch -> NOT latency-bound; pattern-bound. All prior kernels read 256B
// column strips at 32KB stride (DRAM page thrash). R8 re-tiles: each CTA
// reads 4KB CONTIGUOUS per row-chunk (8 col-groups x 64 row-groups). Each
// uint4's four words are four whole outputs for one K-row -> 4 register
// accumulators/thread. Cross-CTA reduce: int REDG into zero-init g_acc +
// per-group ticket; last CTA does epilogue and resets scratch (replay-safe,
// deterministic: int adds are order-independent).

#define K_IN   8192
#define N_OUT  8192
#define NW4    (N_OUT / 4)     // 2048 uint4 per qweight row
#define CG     8               // column groups (1024 outputs each)
#define RG     64              // row groups (16 qweight rows each)
#define RPC    16              // rows per CTA
#define XSF    6553.0f

__device__ int      g_acc[N_OUT];    // zero-init; epilogue re-zeroes each launch
__device__ int      g_xsumi[CG];     // per-group int xsum accumulator; re-zeroed
__device__ unsigned g_tick[CG];      // arrival tickets; re-zeroed

__device__ __forceinline__ int dp2a_lo(int a, unsigned b, int c) {
    int d;
    asm("dp2a.lo.s32.u32 %0, %1, %2, %3;" : "=r"(d) : "r"(a), "r"(b), "r"(c));
    return d;
}
__device__ __forceinline__ int dp2a_hi(int a, unsigned b, int c) {
    int d;
    asm("dp2a.hi.s32.u32 %0, %1, %2, %3;" : "=r"(d) : "r"(a), "r"(b), "r"(c));
    return d;
}

__global__ __launch_bounds__(256, 4)
void qlin4_kernel(const float* __restrict__ x,
                  const uint4* __restrict__ qw,     // [1024, NW4]
                  const float* __restrict__ scales,
                  const float* __restrict__ zeros,
                  const float* __restrict__ bias,
                  float* __restrict__ out)
{
    __shared__ int4 sxp[RPC];      // packed int16 x, one int4 per row
    __shared__ int  ssum[RPC];
    __shared__ unsigned s_old;

    const int tid = threadIdx.x;
    const int cg  = blockIdx.x;    // column group: outputs [cg*1024, +1024)
    const int rg  = blockIdx.y;    // row group: qweight rows [rg*16, +16)

    // ---- Phase 1: pack this CTA's 16 rows of x (128 floats) ----
    if (tid < RPC) {
        const int row = rg * RPC + tid;
        float4 a = __ldg((const float4*)x + 2 * row);
        float4 b = __ldg((const float4*)x + 2 * row + 1);
        int q0 = __float2int_rn(a.x * XSF);
        int q1 = __float2int_rn(a.y * XSF);
        int q2 = __float2int_rn(a.z * XSF);
        int q3 = __float2int_rn(a.w * XSF);
        int q4 = __float2int_rn(b.x * XSF);
        int q5 = __float2int_rn(b.y * XSF);
        int q6 = __float2int_rn(b.z * XSF);
        int q7 = __float2int_rn(b.w * XSF);
        int4 p;
        p.x = (q0 & 0xFFFF) | (q2 << 16);   // even nibbles 0,2 (lo bytes 0,1)
        p.y = (q4 & 0xFFFF) | (q6 << 16);   // even nibbles 4,6 (lo bytes 2,3)
        p.z = (q1 & 0xFFFF) | (q3 << 16);   // odd  nibbles 1,3 (hi bytes 0,1)
        p.w = (q5 & 0xFFFF) | (q7 << 16);   // odd  nibbles 5,7 (hi bytes 2,3)
        sxp[tid]  = p;
        ssum[tid] = q0 + q1 + q2 + q3 + q4 + q5 + q6 + q7;
    }
    __syncthreads();
    if (tid == 0) {
        int t = 0;
#pragma unroll
        for (int r = 0; r < RPC; r++) t += ssum[r];
        atomicAdd(&g_xsumi[cg], t);     // this group's xsum gets all 64 row chunks
    }

    // ---- Phase 2: stream 16 contiguous 4KB row-chunks ----
    // thread t reads uint4 column (cg*256 + t): CTA row-read = 4KB contiguous.
    const uint4* base = qw + (size_t)(rg * RPC) * NW4 + cg * 256 + tid;

    uint4 f0 = __ldg(base);
    uint4 f1 = __ldg(base + NW4);

    int a0 = 0, a1 = 0, a2 = 0, a3 = 0;
#pragma unroll
    for (int r = 0; r < RPC; r++) {
        uint4 q = f0;
        f0 = f1;
        const int pre = (r + 2 < RPC) ? (r + 2) : (RPC - 1);  // branch-free; tail re-loads hit L1
        f1 = __ldg(base + pre * NW4);

        int4 xp = sxp[r];               // broadcast LDS.128

        // word q.x -> output o_base+0, q.y -> +1, q.z -> +2, q.w -> +3
        unsigned lo, hi;
        lo = q.x & 0x0F0F0F0Fu; hi = (q.x >> 4) & 0x0F0F0F0Fu;
        a0 = dp2a_lo(xp.x, lo, a0); a0 = dp2a_hi(xp.y, lo, a0);
        a0 = dp2a_lo(xp.z, hi, a0); a0 = dp2a_hi(xp.w, hi, a0);

        lo = q.y & 0x0F0F0F0Fu; hi = (q.y >> 4) & 0x0F0F0F0Fu;
        a1 = dp2a_lo(xp.x, lo, a1); a1 = dp2a_hi(xp.y, lo, a1);
        a1 = dp2a_lo(xp.z, hi, a1); a1 = dp2a_hi(xp.w, hi, a1);

        lo = q.z & 0x0F0F0F0Fu; hi = (q.z >> 4) & 0x0F0F0F0Fu;
        a2 = dp2a_lo(xp.x, lo, a2); a2 = dp2a_hi(xp.y, lo, a2);
        a2 = dp2a_lo(xp.z, hi, a2); a2 = dp2a_hi(xp.w, hi, a2);

        lo = q.w & 0x0F0F0F0Fu; hi = (q.w >> 4) & 0x0F0F0F0Fu;
        a3 = dp2a_lo(xp.x, lo, a3); a3 = dp2a_hi(xp.y, lo, a3);
        a3 = dp2a_lo(xp.z, hi, a3); a3 = dp2a_hi(xp.w, hi, a3);
    }

    // ---- Phase 3: publish integer partials (REDG, no return) ----
    {
        const int ob = (cg * 256 + tid) * 4;
        atomicAdd(&g_acc[ob + 0], a0);
        atomicAdd(&g_acc[ob + 1], a1);
        atomicAdd(&g_acc[ob + 2], a2);
        atomicAdd(&g_acc[ob + 3], a3);
    }
    __threadfence();                    // release: partials + xsum visible
    __syncthreads();

    // ---- Phase 4: ticket; last CTA of this column group finalizes ----
    if (tid == 0) s_old = atomicAdd(&g_tick[cg], 1u);
    __syncthreads();
    if (s_old == RG - 1) {
        __threadfence();                // acquire
        const float inv  = 1.0f / XSF;
        const float xsum = (float)g_xsumi[cg] * inv;
#pragma unroll
        for (int j = 0; j < 4; j++) {
            const int o = cg * 1024 + j * 256 + tid;    // coalesced
            int s = g_acc[o];
            out[o] = __ldg(bias + o) + __ldg(scales + o) * ((float)s * inv)
                                     - __ldg(zeros  + o) * xsum;
            g_acc[o] = 0;               // reset scratch for next replay
        }
        __syncthreads();
        if (tid == 0) {
            g_xsumi[cg] = 0;
            g_tick[cg]  = 0;
        }
    }
}

extern "C" void kernel_launch(void* const* d_in, const int* in_sizes, int n_in,
                              void* d_out, int out_size)
{
    // metadata order: x, qweight, scales, zeros, bias
    const float* x      = (const float*)d_in[0];
    const uint4* qw     = (const uint4*)d_in[1];
    const float* scales = (const float*)d_in[2];
    const float* zeros  = (const float*)d_in[3];
    const float* bias   = (const float*)d_in[4];
    float* out          = (float*)d_out;

    qlin4_kernel<<<dim3(CG, RG), 256>>>(x, qw, scales, zeros, bias, out);
}